// round 10
// baseline (speedup 1.0000x reference)
#include <cuda_runtime.h>
#include <stdint.h>

#define N_NODES 50000
#define N_EDGES 600000
#define IN_DIM 128
#define HID 256
#define N_CLASSES 16

// ---------------- device scratch (no allocation allowed) ----------------
__device__ int   g_cnt[N_NODES];
__device__ int   g_rowptr[N_NODES + 1];
__device__ int   g_cursor[N_NODES];
__device__ int   g_col[N_EDGES];                  // src ids bucketed by dst
__device__ float g_agg[(size_t)N_NODES * HID];
__device__ float g_h1[(size_t)N_NODES * HID];
__device__ float g_h2[(size_t)N_NODES * HID];
__device__ float g_xt[(size_t)N_NODES * IN_DIM];  // x in tf32
__device__ float g_w1t[2 * IN_DIM * HID];         // [w1_l ; w1_r] tf32
__device__ float g_w2t[2 * HID * HID];            // [w2_l ; w2_r] tf32

// ---------------- helpers ----------------
__device__ __forceinline__ float to_tf32(float x) {
    uint32_t u;
    asm("cvt.rna.tf32.f32 %0, %1;" : "=r"(u) : "f"(x));
    return __uint_as_float(u);
}

__device__ __forceinline__ void mma_tf32(float* d, const uint32_t* a, uint32_t b0, uint32_t b1) {
    asm volatile(
        "mma.sync.aligned.m16n8k8.row.col.f32.tf32.tf32.f32 "
        "{%0,%1,%2,%3}, {%4,%5,%6,%7}, {%8,%9}, {%0,%1,%2,%3};"
        : "+f"(d[0]), "+f"(d[1]), "+f"(d[2]), "+f"(d[3])
        : "r"(a[0]), "r"(a[1]), "r"(a[2]), "r"(a[3]), "r"(b0), "r"(b1));
}

__device__ __forceinline__ void f4add(float4& a, const float4 b) {
    a.x += b.x; a.y += b.y; a.z += b.z; a.w += b.w;
}

// ---------------- launch 1: zero cnt + convert all weights to tf32 ----------------
__global__ void prep_k(const float* __restrict__ w1_l, const float* __restrict__ w1_r,
                       const float* __restrict__ w2_l, const float* __restrict__ w2_r) {
    int i = blockIdx.x * blockDim.x + threadIdx.x;
    if (i < N_NODES) g_cnt[i] = 0;
    const int H1 = IN_DIM * HID;          // 32768
    if (i < 2 * H1)
        g_w1t[i] = to_tf32(i < H1 ? w1_l[i] : w1_r[i - H1]);
    const int H2 = HID * HID;             // 65536
    if (i < 2 * H2)
        g_w2t[i] = to_tf32(i < H2 ? w2_l[i] : w2_r[i - H2]);
}

// ---------------- launch 2: histogram of dst ----------------
__global__ void hist_kernel(const int* __restrict__ ei) {
    int e = blockIdx.x * blockDim.x + threadIdx.x;
    if (e >= N_EDGES) return;
    int d = min(max(ei[N_EDGES + e], 0), N_NODES - 1);
    atomicAdd(&g_cnt[d], 1);
}

// ---------------- launch 3: single-block full scan (1024 thr x 49 elems) ----------------
#define SCAN_T 1024
#define SCAN_CHUNK ((N_NODES + SCAN_T - 1) / SCAN_T)   // 49
__global__ void scan_single_k() {
    __shared__ int sm[SCAN_T];
    int t = threadIdx.x;
    int beg = t * SCAN_CHUNK;
    int end = min(beg + SCAN_CHUNK, N_NODES);
    int local[SCAN_CHUNK];
    int sum = 0;
    for (int i = beg, j = 0; i < end; i++, j++) {
        local[j] = sum;            // exclusive prefix within thread
        sum += g_cnt[i];
    }
    sm[t] = sum;
    __syncthreads();
#pragma unroll
    for (int o = 1; o < SCAN_T; o <<= 1) {
        int u = (t >= o) ? sm[t - o] : 0;
        __syncthreads();
        sm[t] += u;
        __syncthreads();
    }
    int off = sm[t] - sum;         // exclusive offset for this thread's segment
    for (int i = beg, j = 0; i < end; i++, j++) {
        int v = off + local[j];
        g_rowptr[i] = v;
        g_cursor[i] = v;
    }
    if (t == 0) g_rowptr[N_NODES] = N_EDGES;
}

// ---------------- launch 4: fill CSR ----------------
__global__ void fill_kernel(const int* __restrict__ ei) {
    int e = blockIdx.x * blockDim.x + threadIdx.x;
    if (e >= N_EDGES) return;
    int s = min(max(ei[e], 0), N_NODES - 1);
    int d = min(max(ei[N_EDGES + e], 0), N_NODES - 1);
    int pos = atomicAdd(&g_cursor[d], 1);
    g_col[pos] = s;
}

// ---------------- launch 5: gather mean (128) + x tf32 conversion ----------------
__global__ void gather_mean_128(const float* __restrict__ feat) {
    int w = (blockIdx.x * blockDim.x + threadIdx.x) >> 5;
    int lane = threadIdx.x & 31;
    if (w >= N_NODES) return;

    // fused: convert own row of x to tf32
    {
        float4 v = __ldg(reinterpret_cast<const float4*>(feat + (size_t)w * IN_DIM) + lane);
        float4 o;
        o.x = to_tf32(v.x); o.y = to_tf32(v.y); o.z = to_tf32(v.z); o.w = to_tf32(v.w);
        reinterpret_cast<float4*>(g_xt + (size_t)w * IN_DIM)[lane] = o;
    }

    int beg = g_rowptr[w], end = g_rowptr[w + 1];
    float4 acc = make_float4(0.f, 0.f, 0.f, 0.f);
    int j = beg;
    for (; j + 4 <= end; j += 4) {
        int s0 = __ldg(&g_col[j + 0]);
        int s1 = __ldg(&g_col[j + 1]);
        int s2 = __ldg(&g_col[j + 2]);
        int s3 = __ldg(&g_col[j + 3]);
        float4 v0 = __ldg(reinterpret_cast<const float4*>(feat + (size_t)s0 * IN_DIM) + lane);
        float4 v1 = __ldg(reinterpret_cast<const float4*>(feat + (size_t)s1 * IN_DIM) + lane);
        float4 v2 = __ldg(reinterpret_cast<const float4*>(feat + (size_t)s2 * IN_DIM) + lane);
        float4 v3 = __ldg(reinterpret_cast<const float4*>(feat + (size_t)s3 * IN_DIM) + lane);
        f4add(acc, v0); f4add(acc, v1); f4add(acc, v2); f4add(acc, v3);
    }
    for (; j < end; j++) {
        int s = __ldg(&g_col[j]);
        float4 v = __ldg(reinterpret_cast<const float4*>(feat + (size_t)s * IN_DIM) + lane);
        f4add(acc, v);
    }
    float inv = 1.0f / (float)max(end - beg, 1);
    float4 o;
    o.x = to_tf32(acc.x * inv); o.y = to_tf32(acc.y * inv);
    o.z = to_tf32(acc.z * inv); o.w = to_tf32(acc.w * inv);
    reinterpret_cast<float4*>(g_agg + (size_t)w * IN_DIM)[lane] = o;
}

// ---------------- launch 7: gather mean (256) ----------------
__global__ void gather_mean_256() {
    int w = (blockIdx.x * blockDim.x + threadIdx.x) >> 5;
    int lane = threadIdx.x & 31;
    if (w >= N_NODES) return;
    int beg = g_rowptr[w], end = g_rowptr[w + 1];
    float4 a0 = make_float4(0.f, 0.f, 0.f, 0.f), a1 = a0;
    int j = beg;
    for (; j + 4 <= end; j += 4) {
        int s0 = __ldg(&g_col[j + 0]);
        int s1 = __ldg(&g_col[j + 1]);
        int s2 = __ldg(&g_col[j + 2]);
        int s3 = __ldg(&g_col[j + 3]);
        const float4* r0 = reinterpret_cast<const float4*>(g_h1 + (size_t)s0 * HID);
        const float4* r1 = reinterpret_cast<const float4*>(g_h1 + (size_t)s1 * HID);
        const float4* r2 = reinterpret_cast<const float4*>(g_h1 + (size_t)s2 * HID);
        const float4* r3 = reinterpret_cast<const float4*>(g_h1 + (size_t)s3 * HID);
        float4 u0 = __ldg(r0 + lane),      u1 = __ldg(r1 + lane);
        float4 u2 = __ldg(r2 + lane),      u3 = __ldg(r3 + lane);
        float4 v0 = __ldg(r0 + lane + 32), v1 = __ldg(r1 + lane + 32);
        float4 v2 = __ldg(r2 + lane + 32), v3 = __ldg(r3 + lane + 32);
        f4add(a0, u0); f4add(a0, u1); f4add(a0, u2); f4add(a0, u3);
        f4add(a1, v0); f4add(a1, v1); f4add(a1, v2); f4add(a1, v3);
    }
    for (; j < end; j++) {
        int s = __ldg(&g_col[j]);
        const float4* r = reinterpret_cast<const float4*>(g_h1 + (size_t)s * HID);
        f4add(a0, __ldg(r + lane));
        f4add(a1, __ldg(r + lane + 32));
    }
    float inv = 1.0f / (float)max(end - beg, 1);
    float4 o0, o1;
    o0.x = to_tf32(a0.x * inv); o0.y = to_tf32(a0.y * inv);
    o0.z = to_tf32(a0.z * inv); o0.w = to_tf32(a0.w * inv);
    o1.x = to_tf32(a1.x * inv); o1.y = to_tf32(a1.y * inv);
    o1.z = to_tf32(a1.z * inv); o1.w = to_tf32(a1.w * inv);
    float4* dst = reinterpret_cast<float4*>(g_agg + (size_t)w * HID);
    dst[lane] = o0;
    dst[lane + 32] = o1;
}

// ---------------- tf32 tensor-core SAGE GEMM ----------------
#define AS_STRIDE 36
#define BS_STRIDE 136
#define AS_BUF (128 * AS_STRIDE)
#define BS_BUF (32 * BS_STRIDE)

template <int KHALF, bool CVT>
__global__ void __launch_bounds__(256, 2)
sage_tf32(const float* __restrict__ A0, const float* __restrict__ A1,
          const float* __restrict__ W, const float* __restrict__ bias,
          float* __restrict__ C) {
    extern __shared__ float smem[];
    float* As = smem;
    float* Bs = smem + 2 * AS_BUF;

    const int tid = threadIdx.x;
    const int lane = tid & 31;
    const int wid = tid >> 5;
    const int wm = wid & 3;
    const int wn = wid >> 2;
    const int rowBase = blockIdx.x * 128;
    const int colBase = blockIdx.y * 128;
    const int NT = (2 * KHALF) / 32;

    float acc[2][8][4];
#pragma unroll
    for (int i = 0; i < 2; i++)
#pragma unroll
        for (int j = 0; j < 8; j++)
#pragma unroll
            for (int k = 0; k < 4; k++) acc[i][j][k] = 0.0f;

    auto issue = [&](int buf, int k0) {
        float* Asb = As + buf * AS_BUF;
        float* Bsb = Bs + buf * BS_BUF;
        const float* Abase = (k0 < KHALF) ? A0 : A1;
        int kb = (k0 < KHALF) ? k0 : (k0 - KHALF);
#pragma unroll
        for (int i = 0; i < 4; i++) {
            int idx = tid + 256 * i;
            int r = idx >> 3, kc = idx & 7;
            int row = rowBase + r;
            const float* src = Abase + (size_t)row * KHALF + kb + kc * 4;
            uint32_t dst = (uint32_t)__cvta_generic_to_shared(Asb + r * AS_STRIDE + kc * 4);
            int sz = (row < N_NODES) ? 16 : 0;
            asm volatile("cp.async.ca.shared.global [%0], [%1], 16, %2;"
                         :: "r"(dst), "l"(src), "r"(sz));
        }
#pragma unroll
        for (int i = 0; i < 4; i++) {
            int idx = tid + 256 * i;
            int k = idx >> 5, c4 = idx & 31;
            const float* src = W + (size_t)(k0 + k) * HID + colBase + c4 * 4;
            uint32_t dst = (uint32_t)__cvta_generic_to_shared(Bsb + k * BS_STRIDE + c4 * 4);
            asm volatile("cp.async.ca.shared.global [%0], [%1], 16;"
                         :: "r"(dst), "l"(src));
        }
        asm volatile("cp.async.commit_group;");
    };

    issue(0, 0);
    for (int t = 0; t < NT; t++) {
        if (t + 1 < NT) {
            issue((t + 1) & 1, (t + 1) * 32);
            asm volatile("cp.async.wait_group 1;");
        } else {
            asm volatile("cp.async.wait_group 0;");
        }
        __syncthreads();
        const float* Asb = As + (t & 1) * AS_BUF;
        const float* Bsb = Bs + (t & 1) * BS_BUF;
#pragma unroll
        for (int k8 = 0; k8 < 4; k8++) {
            int kb = k8 * 8;
            uint32_t a[2][4];
#pragma unroll
            for (int mt = 0; mt < 2; mt++) {
                int m = wm * 32 + mt * 16 + (lane >> 2);
                int k = kb + (lane & 3);
                a[mt][0] = __float_as_uint(Asb[m * AS_STRIDE + k]);
                a[mt][1] = __float_as_uint(Asb[(m + 8) * AS_STRIDE + k]);
                a[mt][2] = __float_as_uint(Asb[m * AS_STRIDE + k + 4]);
                a[mt][3] = __float_as_uint(Asb[(m + 8) * AS_STRIDE + k + 4]);
            }
#pragma unroll
            for (int nt = 0; nt < 8; nt++) {
                int n = wn * 64 + nt * 8 + (lane >> 2);
                int k = kb + (lane & 3);
                uint32_t b0 = __float_as_uint(Bsb[k * BS_STRIDE + n]);
                uint32_t b1 = __float_as_uint(Bsb[(k + 4) * BS_STRIDE + n]);
                mma_tf32(acc[0][nt], a[0], b0, b1);
                mma_tf32(acc[1][nt], a[1], b0, b1);
            }
        }
        __syncthreads();
    }

#pragma unroll
    for (int mt = 0; mt < 2; mt++) {
        int r0 = rowBase + wm * 32 + mt * 16 + (lane >> 2);
#pragma unroll
        for (int nt = 0; nt < 8; nt++) {
            int c = colBase + wn * 64 + nt * 8 + (lane & 3) * 2;
            float bv0 = __ldg(bias + c);
            float bv1 = __ldg(bias + c + 1);
            float v0 = fmaxf(acc[mt][nt][0] + bv0, 0.0f);
            float v1 = fmaxf(acc[mt][nt][1] + bv1, 0.0f);
            float v2 = fmaxf(acc[mt][nt][2] + bv0, 0.0f);
            float v3 = fmaxf(acc[mt][nt][3] + bv1, 0.0f);
            if (CVT) {
                v0 = to_tf32(v0); v1 = to_tf32(v1);
                v2 = to_tf32(v2); v3 = to_tf32(v3);
            }
            if (r0 < N_NODES)
                *reinterpret_cast<float2*>(C + (size_t)r0 * HID + c) = make_float2(v0, v1);
            if (r0 + 8 < N_NODES)
                *reinterpret_cast<float2*>(C + (size_t)(r0 + 8) * HID + c) = make_float2(v2, v3);
        }
    }
}

// ---------------- launch 9: classifier ----------------
__global__ void classifier_k(const float* __restrict__ wc,
                             const float* __restrict__ bc,
                             float* __restrict__ out) {
    __shared__ float w[HID * N_CLASSES];
    __shared__ float hrow[8][HID];
    for (int i = threadIdx.x; i < HID * N_CLASSES; i += blockDim.x)
        w[i] = wc[i];
    __syncthreads();

    int warp = threadIdx.x >> 5;
    int lane = threadIdx.x & 31;
    int row = blockIdx.x * 8 + warp;
    if (row >= N_NODES) return;

    const float* h = g_h2 + (size_t)row * HID;
    for (int k = lane; k < HID; k += 32) hrow[warp][k] = h[k];
    __syncwarp();

    int c = lane & 15;
    int p = lane >> 4;
    float acc = 0.0f;
    int kbeg = p * (HID / 2);
#pragma unroll 8
    for (int k = kbeg; k < kbeg + HID / 2; k++)
        acc += hrow[warp][k] * w[k * N_CLASSES + c];
    acc += __shfl_xor_sync(0xffffffffu, acc, 16);
    if (lane < 16) out[(size_t)row * N_CLASSES + lane] = acc + bc[lane];
}

// ---------------- launch ----------------
extern "C" void kernel_launch(void* const* d_in, const int* in_sizes, int n_in,
                              void* d_out, int out_size) {
    const float* x    = (const float*)d_in[0];
    const int*   ei   = (const int*)d_in[1];
    const float* w1_l = (const float*)d_in[2];
    const float* b1_l = (const float*)d_in[3];
    const float* w1_r = (const float*)d_in[4];
    const float* w2_l = (const float*)d_in[5];
    const float* b2_l = (const float*)d_in[6];
    const float* w2_r = (const float*)d_in[7];
    const float* wc   = (const float*)d_in[8];
    const float* bc   = (const float*)d_in[9];
    float* out = (float*)d_out;

    // resolve REAL device addresses (GB300 ATS pitfall: never pass symbols as args)
    void *p_agg, *p_h1, *p_h2, *p_xt, *p_w1t, *p_w2t;
    cudaGetSymbolAddress(&p_agg, g_agg);
    cudaGetSymbolAddress(&p_h1,  g_h1);
    cudaGetSymbolAddress(&p_h2,  g_h2);
    cudaGetSymbolAddress(&p_xt,  g_xt);
    cudaGetSymbolAddress(&p_w1t, g_w1t);
    cudaGetSymbolAddress(&p_w2t, g_w2t);

    const int SMEM = (2 * AS_BUF + 2 * BS_BUF) * 4;
    cudaFuncSetAttribute(sage_tf32<IN_DIM, true>,
                         cudaFuncAttributeMaxDynamicSharedMemorySize, SMEM);
    cudaFuncSetAttribute(sage_tf32<HID, false>,
                         cudaFuncAttributeMaxDynamicSharedMemorySize, SMEM);

    // 1: zero cnt + weight cvts
    prep_k<<<(2 * HID * HID + 255) / 256, 256>>>(w1_l, w1_r, w2_l, w2_r);
    // 2: histogram
    hist_kernel<<<(N_EDGES + 255) / 256, 256>>>(ei);
    // 3: scan
    scan_single_k<<<1, SCAN_T>>>();
    // 4: fill
    fill_kernel<<<(N_EDGES + 255) / 256, 256>>>(ei);
    // 5: gather layer1 + x cvt
    gather_mean_128<<<(N_NODES * 32 + 255) / 256, 256>>>(x);
    // 6: GEMM layer1  <-- ncu -s 5 -c 1 captures this launch
    {
        dim3 grid((N_NODES + 127) / 128, HID / 128);
        sage_tf32<IN_DIM, true><<<grid, 256, SMEM>>>(
            (const float*)p_agg, (const float*)p_xt, (const float*)p_w1t, b1_l, (float*)p_h1);
    }
    // 7: gather layer2
    gather_mean_256<<<(N_NODES * 32 + 255) / 256, 256>>>();
    // 8: GEMM layer2
    {
        dim3 grid((N_NODES + 127) / 128, HID / 128);
        sage_tf32<HID, false><<<grid, 256, SMEM>>>(
            (const float*)p_agg, (const float*)p_h1, (const float*)p_w2t, b2_l, (float*)p_h2);
    }
    // 9: classifier
    classifier_k<<<(N_NODES + 7) / 8, 256>>>(wc, bc, out);
}

// round 11
// speedup vs baseline: 1.1134x; 1.1134x over previous
#include <cuda_runtime.h>
#include <stdint.h>

#define N_NODES 50000
#define N_EDGES 600000
#define IN_DIM 128
#define HID 256
#define N_CLASSES 16

#define SCAN_BLOCK 256
#define N_SBLOCKS ((N_NODES + SCAN_BLOCK - 1) / SCAN_BLOCK)   // 196

// ---------------- device scratch (no allocation allowed) ----------------
__device__ int   g_cnt[N_NODES];
__device__ int   g_blockoff[N_SBLOCKS];
__device__ int   g_rowptr[N_NODES + 1];
__device__ int   g_cursor[N_NODES];
__device__ int   g_col[N_EDGES];                  // src ids bucketed by dst
__device__ float g_agg[(size_t)N_NODES * HID];
__device__ float g_h1[(size_t)N_NODES * HID];
__device__ float g_h2[(size_t)N_NODES * HID];
__device__ float g_xt[(size_t)N_NODES * IN_DIM];  // x in tf32
__device__ float g_w1t[2 * IN_DIM * HID];         // [w1_l ; w1_r] tf32
__device__ float g_w2t[2 * HID * HID];            // [w2_l ; w2_r] tf32

// ---------------- helpers ----------------
__device__ __forceinline__ float to_tf32(float x) {
    uint32_t u;
    asm("cvt.rna.tf32.f32 %0, %1;" : "=r"(u) : "f"(x));
    return __uint_as_float(u);
}

__device__ __forceinline__ void mma_tf32(float* d, const uint32_t* a, uint32_t b0, uint32_t b1) {
    asm volatile(
        "mma.sync.aligned.m16n8k8.row.col.f32.tf32.tf32.f32 "
        "{%0,%1,%2,%3}, {%4,%5,%6,%7}, {%8,%9}, {%0,%1,%2,%3};"
        : "+f"(d[0]), "+f"(d[1]), "+f"(d[2]), "+f"(d[3])
        : "r"(a[0]), "r"(a[1]), "r"(a[2]), "r"(a[3]), "r"(b0), "r"(b1));
}

__device__ __forceinline__ void f4add(float4& a, const float4 b) {
    a.x += b.x; a.y += b.y; a.z += b.z; a.w += b.w;
}

// ---------------- CSR build ----------------
__global__ void zero_cnt() {
    int i = blockIdx.x * blockDim.x + threadIdx.x;
    if (i < N_NODES) g_cnt[i] = 0;
}
__global__ void hist_kernel(const int* __restrict__ ei) {
    int e = blockIdx.x * blockDim.x + threadIdx.x;
    if (e >= N_EDGES) return;
    int d = min(max(ei[N_EDGES + e], 0), N_NODES - 1);
    atomicAdd(&g_cnt[d], 1);
}
// hierarchical scan: (1) per-block reduce, (2) scan block sums, (3) per-block scan + offset
__global__ void block_reduce_k() {
    __shared__ int sm[SCAN_BLOCK];
    int i = blockIdx.x * SCAN_BLOCK + threadIdx.x;
    sm[threadIdx.x] = (i < N_NODES) ? g_cnt[i] : 0;
    __syncthreads();
#pragma unroll
    for (int o = SCAN_BLOCK / 2; o > 0; o >>= 1) {
        if (threadIdx.x < o) sm[threadIdx.x] += sm[threadIdx.x + o];
        __syncthreads();
    }
    if (threadIdx.x == 0) g_blockoff[blockIdx.x] = sm[0];
}
__global__ void scan_blocksums_k() {
    __shared__ int sm[256];
    int t = threadIdx.x;
    int v = (t < N_SBLOCKS) ? g_blockoff[t] : 0;
    sm[t] = v;
    __syncthreads();
#pragma unroll
    for (int o = 1; o < 256; o <<= 1) {
        int u = (t >= o) ? sm[t - o] : 0;
        __syncthreads();
        sm[t] += u;
        __syncthreads();
    }
    if (t < N_SBLOCKS) g_blockoff[t] = sm[t] - v;
}
__global__ void block_scan_k() {
    __shared__ int sm[SCAN_BLOCK];
    int i = blockIdx.x * SCAN_BLOCK + threadIdx.x;
    int v = (i < N_NODES) ? g_cnt[i] : 0;
    sm[threadIdx.x] = v;
    __syncthreads();
#pragma unroll
    for (int o = 1; o < SCAN_BLOCK; o <<= 1) {
        int u = (threadIdx.x >= o) ? sm[threadIdx.x - o] : 0;
        __syncthreads();
        sm[threadIdx.x] += u;
        __syncthreads();
    }
    if (i < N_NODES) {
        int excl = sm[threadIdx.x] - v + g_blockoff[blockIdx.x];
        g_rowptr[i] = excl;
        g_cursor[i] = excl;
    }
    if (i == 0) g_rowptr[N_NODES] = N_EDGES;
}
__global__ void fill_kernel(const int* __restrict__ ei) {
    int e = blockIdx.x * blockDim.x + threadIdx.x;
    if (e >= N_EDGES) return;
    int s = min(max(ei[e], 0), N_NODES - 1);
    int d = min(max(ei[N_EDGES + e], 0), N_NODES - 1);
    int pos = atomicAdd(&g_cursor[d], 1);
    g_col[pos] = s;
}

// ---------------- tf32 conversion of inputs ----------------
__global__ void cvt_copy(float* __restrict__ dst, const float* __restrict__ src, int n) {
    int i = blockIdx.x * blockDim.x + threadIdx.x;
    if (i < n) dst[i] = to_tf32(src[i]);
}
__global__ void cvt_concat(float* __restrict__ dst, const float* __restrict__ a,
                           const float* __restrict__ b, int half_elems) {
    int i = blockIdx.x * blockDim.x + threadIdx.x;
    if (i >= 2 * half_elems) return;
    float v = (i < half_elems) ? a[i] : b[i - half_elems];
    dst[i] = to_tf32(v);
}

// ---------------- gather mean (CSR), warp per node, 4-edge unroll ----------------
__global__ void gather_mean_128(const float* __restrict__ feat) {
    int w = (blockIdx.x * blockDim.x + threadIdx.x) >> 5;
    int lane = threadIdx.x & 31;
    if (w >= N_NODES) return;
    int beg = g_rowptr[w], end = g_rowptr[w + 1];
    float4 acc = make_float4(0.f, 0.f, 0.f, 0.f);
    int j = beg;
    for (; j + 4 <= end; j += 4) {
        int s0 = __ldg(&g_col[j + 0]);
        int s1 = __ldg(&g_col[j + 1]);
        int s2 = __ldg(&g_col[j + 2]);
        int s3 = __ldg(&g_col[j + 3]);
        float4 v0 = __ldg(reinterpret_cast<const float4*>(feat + (size_t)s0 * IN_DIM) + lane);
        float4 v1 = __ldg(reinterpret_cast<const float4*>(feat + (size_t)s1 * IN_DIM) + lane);
        float4 v2 = __ldg(reinterpret_cast<const float4*>(feat + (size_t)s2 * IN_DIM) + lane);
        float4 v3 = __ldg(reinterpret_cast<const float4*>(feat + (size_t)s3 * IN_DIM) + lane);
        f4add(acc, v0); f4add(acc, v1); f4add(acc, v2); f4add(acc, v3);
    }
    for (; j < end; j++) {
        int s = __ldg(&g_col[j]);
        float4 v = __ldg(reinterpret_cast<const float4*>(feat + (size_t)s * IN_DIM) + lane);
        f4add(acc, v);
    }
    float inv = 1.0f / (float)max(end - beg, 1);
    float4 o;
    o.x = to_tf32(acc.x * inv); o.y = to_tf32(acc.y * inv);
    o.z = to_tf32(acc.z * inv); o.w = to_tf32(acc.w * inv);
    reinterpret_cast<float4*>(g_agg + (size_t)w * IN_DIM)[lane] = o;
}

// two warps per node: warp-half h handles float4s [h*32 .. h*32+31] of the 256-wide row
__global__ void gather_mean_256() {
    int gw = (blockIdx.x * blockDim.x + threadIdx.x) >> 5;
    int node = gw >> 1;
    int half = gw & 1;
    int lane = threadIdx.x & 31;
    if (node >= N_NODES) return;
    int beg = g_rowptr[node], end = g_rowptr[node + 1];
    int fo = half * 32 + lane;                     // float4 offset within row (0..63)
    const float4* h1v = reinterpret_cast<const float4*>(g_h1);
    float4 acc = make_float4(0.f, 0.f, 0.f, 0.f);
    int j = beg;
    for (; j + 4 <= end; j += 4) {
        int s0 = __ldg(&g_col[j + 0]);
        int s1 = __ldg(&g_col[j + 1]);
        int s2 = __ldg(&g_col[j + 2]);
        int s3 = __ldg(&g_col[j + 3]);
        float4 v0 = __ldg(h1v + (size_t)s0 * (HID / 4) + fo);
        float4 v1 = __ldg(h1v + (size_t)s1 * (HID / 4) + fo);
        float4 v2 = __ldg(h1v + (size_t)s2 * (HID / 4) + fo);
        float4 v3 = __ldg(h1v + (size_t)s3 * (HID / 4) + fo);
        f4add(acc, v0); f4add(acc, v1); f4add(acc, v2); f4add(acc, v3);
    }
    for (; j < end; j++) {
        int s = __ldg(&g_col[j]);
        f4add(acc, __ldg(h1v + (size_t)s * (HID / 4) + fo));
    }
    float inv = 1.0f / (float)max(end - beg, 1);
    float4 o;
    o.x = to_tf32(acc.x * inv); o.y = to_tf32(acc.y * inv);
    o.z = to_tf32(acc.z * inv); o.w = to_tf32(acc.w * inv);
    reinterpret_cast<float4*>(g_agg)[(size_t)node * (HID / 4) + fo] = o;
}

// ---------------- tf32 tensor-core SAGE GEMM ----------------
#define AS_STRIDE 36
#define BS_STRIDE 136
#define AS_BUF (128 * AS_STRIDE)
#define BS_BUF (32 * BS_STRIDE)

template <int KHALF, bool CVT>
__global__ void __launch_bounds__(256, 2)
sage_tf32(const float* __restrict__ A0, const float* __restrict__ A1,
          const float* __restrict__ W, const float* __restrict__ bias,
          float* __restrict__ C) {
    extern __shared__ float smem[];
    float* As = smem;
    float* Bs = smem + 2 * AS_BUF;

    const int tid = threadIdx.x;
    const int lane = tid & 31;
    const int wid = tid >> 5;
    const int wm = wid & 3;
    const int wn = wid >> 2;
    const int rowBase = blockIdx.x * 128;
    const int colBase = blockIdx.y * 128;
    const int NT = (2 * KHALF) / 32;

    float acc[2][8][4];
#pragma unroll
    for (int i = 0; i < 2; i++)
#pragma unroll
        for (int j = 0; j < 8; j++)
#pragma unroll
            for (int k = 0; k < 4; k++) acc[i][j][k] = 0.0f;

    auto issue = [&](int buf, int k0) {
        float* Asb = As + buf * AS_BUF;
        float* Bsb = Bs + buf * BS_BUF;
        const float* Abase = (k0 < KHALF) ? A0 : A1;
        int kb = (k0 < KHALF) ? k0 : (k0 - KHALF);
#pragma unroll
        for (int i = 0; i < 4; i++) {
            int idx = tid + 256 * i;
            int r = idx >> 3, kc = idx & 7;
            int row = rowBase + r;
            const float* src = Abase + (size_t)row * KHALF + kb + kc * 4;
            uint32_t dst = (uint32_t)__cvta_generic_to_shared(Asb + r * AS_STRIDE + kc * 4);
            int sz = (row < N_NODES) ? 16 : 0;
            asm volatile("cp.async.ca.shared.global [%0], [%1], 16, %2;"
                         :: "r"(dst), "l"(src), "r"(sz));
        }
#pragma unroll
        for (int i = 0; i < 4; i++) {
            int idx = tid + 256 * i;
            int k = idx >> 5, c4 = idx & 31;
            const float* src = W + (size_t)(k0 + k) * HID + colBase + c4 * 4;
            uint32_t dst = (uint32_t)__cvta_generic_to_shared(Bsb + k * BS_STRIDE + c4 * 4);
            asm volatile("cp.async.ca.shared.global [%0], [%1], 16;"
                         :: "r"(dst), "l"(src));
        }
        asm volatile("cp.async.commit_group;");
    };

    issue(0, 0);
    for (int t = 0; t < NT; t++) {
        if (t + 1 < NT) {
            issue((t + 1) & 1, (t + 1) * 32);
            asm volatile("cp.async.wait_group 1;");
        } else {
            asm volatile("cp.async.wait_group 0;");
        }
        __syncthreads();
        const float* Asb = As + (t & 1) * AS_BUF;
        const float* Bsb = Bs + (t & 1) * BS_BUF;
#pragma unroll
        for (int k8 = 0; k8 < 4; k8++) {
            int kb = k8 * 8;
            uint32_t a[2][4];
#pragma unroll
            for (int mt = 0; mt < 2; mt++) {
                int m = wm * 32 + mt * 16 + (lane >> 2);
                int k = kb + (lane & 3);
                a[mt][0] = __float_as_uint(Asb[m * AS_STRIDE + k]);
                a[mt][1] = __float_as_uint(Asb[(m + 8) * AS_STRIDE + k]);
                a[mt][2] = __float_as_uint(Asb[m * AS_STRIDE + k + 4]);
                a[mt][3] = __float_as_uint(Asb[(m + 8) * AS_STRIDE + k + 4]);
            }
#pragma unroll
            for (int nt = 0; nt < 8; nt++) {
                int n = wn * 64 + nt * 8 + (lane >> 2);
                int k = kb + (lane & 3);
                uint32_t b0 = __float_as_uint(Bsb[k * BS_STRIDE + n]);
                uint32_t b1 = __float_as_uint(Bsb[(k + 4) * BS_STRIDE + n]);
                mma_tf32(acc[0][nt], a[0], b0, b1);
                mma_tf32(acc[1][nt], a[1], b0, b1);
            }
        }
        __syncthreads();
    }

#pragma unroll
    for (int mt = 0; mt < 2; mt++) {
        int r0 = rowBase + wm * 32 + mt * 16 + (lane >> 2);
#pragma unroll
        for (int nt = 0; nt < 8; nt++) {
            int c = colBase + wn * 64 + nt * 8 + (lane & 3) * 2;
            float bv0 = __ldg(bias + c);
            float bv1 = __ldg(bias + c + 1);
            float v0 = fmaxf(acc[mt][nt][0] + bv0, 0.0f);
            float v1 = fmaxf(acc[mt][nt][1] + bv1, 0.0f);
            float v2 = fmaxf(acc[mt][nt][2] + bv0, 0.0f);
            float v3 = fmaxf(acc[mt][nt][3] + bv1, 0.0f);
            if (CVT) {
                v0 = to_tf32(v0); v1 = to_tf32(v1);
                v2 = to_tf32(v2); v3 = to_tf32(v3);
            }
            if (r0 < N_NODES)
                *reinterpret_cast<float2*>(C + (size_t)r0 * HID + c) = make_float2(v0, v1);
            if (r0 + 8 < N_NODES)
                *reinterpret_cast<float2*>(C + (size_t)(r0 + 8) * HID + c) = make_float2(v2, v3);
        }
    }
}

// ---------------- classifier ----------------
__global__ void classifier_k(const float* __restrict__ wc,
                             const float* __restrict__ bc,
                             float* __restrict__ out) {
    __shared__ float w[HID * N_CLASSES];
    __shared__ float hrow[8][HID];
    for (int i = threadIdx.x; i < HID * N_CLASSES; i += blockDim.x)
        w[i] = wc[i];
    __syncthreads();

    int warp = threadIdx.x >> 5;
    int lane = threadIdx.x & 31;
    int row = blockIdx.x * 8 + warp;
    if (row >= N_NODES) return;

    const float* h = g_h2 + (size_t)row * HID;
    for (int k = lane; k < HID; k += 32) hrow[warp][k] = h[k];
    __syncwarp();

    int c = lane & 15;
    int p = lane >> 4;
    float acc = 0.0f;
    int kbeg = p * (HID / 2);
#pragma unroll 8
    for (int k = kbeg; k < kbeg + HID / 2; k++)
        acc += hrow[warp][k] * w[k * N_CLASSES + c];
    acc += __shfl_xor_sync(0xffffffffu, acc, 16);
    if (lane < 16) out[(size_t)row * N_CLASSES + lane] = acc + bc[lane];
}

// ---------------- launch ----------------
extern "C" void kernel_launch(void* const* d_in, const int* in_sizes, int n_in,
                              void* d_out, int out_size) {
    const float* x    = (const float*)d_in[0];
    const int*   ei   = (const int*)d_in[1];
    const float* w1_l = (const float*)d_in[2];
    const float* b1_l = (const float*)d_in[3];
    const float* w1_r = (const float*)d_in[4];
    const float* w2_l = (const float*)d_in[5];
    const float* b2_l = (const float*)d_in[6];
    const float* w2_r = (const float*)d_in[7];
    const float* wc   = (const float*)d_in[8];
    const float* bc   = (const float*)d_in[9];
    float* out = (float*)d_out;

    // resolve REAL device addresses (GB300 ATS pitfall: never pass symbols as args)
    void *p_agg, *p_h1, *p_h2, *p_xt, *p_w1t, *p_w2t;
    cudaGetSymbolAddress(&p_agg, g_agg);
    cudaGetSymbolAddress(&p_h1,  g_h1);
    cudaGetSymbolAddress(&p_h2,  g_h2);
    cudaGetSymbolAddress(&p_xt,  g_xt);
    cudaGetSymbolAddress(&p_w1t, g_w1t);
    cudaGetSymbolAddress(&p_w2t, g_w2t);

    const int SMEM = (2 * AS_BUF + 2 * BS_BUF) * 4;
    cudaFuncSetAttribute(sage_tf32<IN_DIM, true>,
                         cudaFuncAttributeMaxDynamicSharedMemorySize, SMEM);
    cudaFuncSetAttribute(sage_tf32<HID, false>,
                         cudaFuncAttributeMaxDynamicSharedMemorySize, SMEM);

    // ---- CSR build ----
    zero_cnt<<<(N_NODES + 255) / 256, 256>>>();
    hist_kernel<<<(N_EDGES + 255) / 256, 256>>>(ei);
    block_reduce_k<<<N_SBLOCKS, SCAN_BLOCK>>>();
    scan_blocksums_k<<<1, 256>>>();
    block_scan_k<<<N_SBLOCKS, SCAN_BLOCK>>>();
    fill_kernel<<<(N_EDGES + 255) / 256, 256>>>(ei);

    // ---- tf32 input conversions ----
    cvt_concat<<<(2 * IN_DIM * HID + 255) / 256, 256>>>((float*)p_w1t, w1_l, w1_r, IN_DIM * HID);
    cvt_concat<<<(2 * HID * HID + 255) / 256, 256>>>((float*)p_w2t, w2_l, w2_r, HID * HID);
    cvt_copy<<<(N_NODES * IN_DIM + 255) / 256, 256>>>((float*)p_xt, x, N_NODES * IN_DIM);

    // ---- layer 1 ----
    gather_mean_128<<<(N_NODES * 32 + 255) / 256, 256>>>(x);
    {
        dim3 grid((N_NODES + 127) / 128, HID / 128);
        sage_tf32<IN_DIM, true><<<grid, 256, SMEM>>>(
            (const float*)p_agg, (const float*)p_xt, (const float*)p_w1t, b1_l, (float*)p_h1);
    }

    // ---- layer 2 ----
    gather_mean_256<<<(N_NODES * 2 * 32 + 255) / 256, 256>>>();
    {
        dim3 grid((N_NODES + 127) / 128, HID / 128);
        sage_tf32<HID, false><<<grid, 256, SMEM>>>(
            (const float*)p_agg, (const float*)p_h1, (const float*)p_w2t, b2_l, (float*)p_h2);
    }

    // ---- classifier ----
    classifier_k<<<(N_NODES + 7) / 8, 256>>>(wc, bc, out);
}

// round 12
// speedup vs baseline: 1.1206x; 1.0065x over previous
#include <cuda_runtime.h>
#include <stdint.h>

#define N_NODES 50000
#define N_EDGES 600000
#define IN_DIM 128
#define HID 256
#define N_CLASSES 16

#define SCAN_BLOCK 256
#define N_SBLOCKS ((N_NODES + SCAN_BLOCK - 1) / SCAN_BLOCK)   // 196

// ---------------- device scratch (no allocation allowed) ----------------
__device__ int   g_cnt[N_NODES];
__device__ int   g_blockoff[N_SBLOCKS];
__device__ int   g_rowptr[N_NODES + 1];
__device__ int   g_cursor[N_NODES];
__device__ int   g_col[N_EDGES];                  // src ids bucketed by dst
__device__ float g_agg[(size_t)N_NODES * HID];
__device__ float g_h1[(size_t)N_NODES * HID];
__device__ float g_h2[(size_t)N_NODES * HID];
__device__ float g_xt[(size_t)N_NODES * IN_DIM];  // x in tf32
__device__ float g_w1t[2 * IN_DIM * HID];         // [w1_l ; w1_r] tf32
__device__ float g_w2t[2 * HID * HID];            // [w2_l ; w2_r] tf32

// ---------------- helpers ----------------
__device__ __forceinline__ float to_tf32(float x) {
    uint32_t u;
    asm("cvt.rna.tf32.f32 %0, %1;" : "=r"(u) : "f"(x));
    return __uint_as_float(u);
}

__device__ __forceinline__ void mma_tf32(float* d, const uint32_t* a, uint32_t b0, uint32_t b1) {
    asm volatile(
        "mma.sync.aligned.m16n8k8.row.col.f32.tf32.tf32.f32 "
        "{%0,%1,%2,%3}, {%4,%5,%6,%7}, {%8,%9}, {%0,%1,%2,%3};"
        : "+f"(d[0]), "+f"(d[1]), "+f"(d[2]), "+f"(d[3])
        : "r"(a[0]), "r"(a[1]), "r"(a[2]), "r"(a[3]), "r"(b0), "r"(b1));
}

__device__ __forceinline__ void f4add(float4& a, const float4 b) {
    a.x += b.x; a.y += b.y; a.z += b.z; a.w += b.w;
}

// ---------------- CSR build ----------------
__global__ void zero_cnt() {
    int i = blockIdx.x * blockDim.x + threadIdx.x;
    if (i < N_NODES) g_cnt[i] = 0;
}
__global__ void hist_kernel(const int* __restrict__ ei) {
    int e = blockIdx.x * blockDim.x + threadIdx.x;
    if (e >= N_EDGES) return;
    int d = min(max(ei[N_EDGES + e], 0), N_NODES - 1);
    atomicAdd(&g_cnt[d], 1);
}
// hierarchical scan: (1) per-block reduce, (2) scan block sums, (3) per-block scan + offset
__global__ void block_reduce_k() {
    __shared__ int sm[SCAN_BLOCK];
    int i = blockIdx.x * SCAN_BLOCK + threadIdx.x;
    sm[threadIdx.x] = (i < N_NODES) ? g_cnt[i] : 0;
    __syncthreads();
#pragma unroll
    for (int o = SCAN_BLOCK / 2; o > 0; o >>= 1) {
        if (threadIdx.x < o) sm[threadIdx.x] += sm[threadIdx.x + o];
        __syncthreads();
    }
    if (threadIdx.x == 0) g_blockoff[blockIdx.x] = sm[0];
}
__global__ void scan_blocksums_k() {
    __shared__ int sm[256];
    int t = threadIdx.x;
    int v = (t < N_SBLOCKS) ? g_blockoff[t] : 0;
    sm[t] = v;
    __syncthreads();
#pragma unroll
    for (int o = 1; o < 256; o <<= 1) {
        int u = (t >= o) ? sm[t - o] : 0;
        __syncthreads();
        sm[t] += u;
        __syncthreads();
    }
    if (t < N_SBLOCKS) g_blockoff[t] = sm[t] - v;
}
__global__ void block_scan_k() {
    __shared__ int sm[SCAN_BLOCK];
    int i = blockIdx.x * SCAN_BLOCK + threadIdx.x;
    int v = (i < N_NODES) ? g_cnt[i] : 0;
    sm[threadIdx.x] = v;
    __syncthreads();
#pragma unroll
    for (int o = 1; o < SCAN_BLOCK; o <<= 1) {
        int u = (threadIdx.x >= o) ? sm[threadIdx.x - o] : 0;
        __syncthreads();
        sm[threadIdx.x] += u;
        __syncthreads();
    }
    if (i < N_NODES) {
        int excl = sm[threadIdx.x] - v + g_blockoff[blockIdx.x];
        g_rowptr[i] = excl;
        g_cursor[i] = excl;
    }
    if (i == 0) g_rowptr[N_NODES] = N_EDGES;
}
__global__ void fill_kernel(const int* __restrict__ ei) {
    int e = blockIdx.x * blockDim.x + threadIdx.x;
    if (e >= N_EDGES) return;
    int s = min(max(ei[e], 0), N_NODES - 1);
    int d = min(max(ei[N_EDGES + e], 0), N_NODES - 1);
    int pos = atomicAdd(&g_cursor[d], 1);
    g_col[pos] = s;
}

// ---------------- tf32 conversion of inputs ----------------
__global__ void cvt_copy(float* __restrict__ dst, const float* __restrict__ src, int n) {
    int i = blockIdx.x * blockDim.x + threadIdx.x;
    if (i < n) dst[i] = to_tf32(src[i]);
}
__global__ void cvt_concat(float* __restrict__ dst, const float* __restrict__ a,
                           const float* __restrict__ b, int half_elems) {
    int i = blockIdx.x * blockDim.x + threadIdx.x;
    if (i >= 2 * half_elems) return;
    float v = (i < half_elems) ? a[i] : b[i - half_elems];
    dst[i] = to_tf32(v);
}

// ---------------- gather mean (CSR), warp per node, 4-edge unroll ----------------
__global__ void gather_mean_128(const float* __restrict__ feat) {
    int w = (blockIdx.x * blockDim.x + threadIdx.x) >> 5;
    int lane = threadIdx.x & 31;
    if (w >= N_NODES) return;
    int beg = g_rowptr[w], end = g_rowptr[w + 1];
    float4 acc = make_float4(0.f, 0.f, 0.f, 0.f);
    int j = beg;
    for (; j + 4 <= end; j += 4) {
        int s0 = __ldg(&g_col[j + 0]);
        int s1 = __ldg(&g_col[j + 1]);
        int s2 = __ldg(&g_col[j + 2]);
        int s3 = __ldg(&g_col[j + 3]);
        float4 v0 = __ldg(reinterpret_cast<const float4*>(feat + (size_t)s0 * IN_DIM) + lane);
        float4 v1 = __ldg(reinterpret_cast<const float4*>(feat + (size_t)s1 * IN_DIM) + lane);
        float4 v2 = __ldg(reinterpret_cast<const float4*>(feat + (size_t)s2 * IN_DIM) + lane);
        float4 v3 = __ldg(reinterpret_cast<const float4*>(feat + (size_t)s3 * IN_DIM) + lane);
        f4add(acc, v0); f4add(acc, v1); f4add(acc, v2); f4add(acc, v3);
    }
    for (; j < end; j++) {
        int s = __ldg(&g_col[j]);
        float4 v = __ldg(reinterpret_cast<const float4*>(feat + (size_t)s * IN_DIM) + lane);
        f4add(acc, v);
    }
    float inv = 1.0f / (float)max(end - beg, 1);
    float4 o;
    o.x = to_tf32(acc.x * inv); o.y = to_tf32(acc.y * inv);
    o.z = to_tf32(acc.z * inv); o.w = to_tf32(acc.w * inv);
    reinterpret_cast<float4*>(g_agg + (size_t)w * IN_DIM)[lane] = o;
}

// two warps per node: warp-half h handles float4s [h*32 .. h*32+31] of the 256-wide row
__global__ void gather_mean_256() {
    int gw = (blockIdx.x * blockDim.x + threadIdx.x) >> 5;
    int node = gw >> 1;
    int half = gw & 1;
    int lane = threadIdx.x & 31;
    if (node >= N_NODES) return;
    int beg = g_rowptr[node], end = g_rowptr[node + 1];
    int fo = half * 32 + lane;                     // float4 offset within row (0..63)
    const float4* h1v = reinterpret_cast<const float4*>(g_h1);
    float4 acc = make_float4(0.f, 0.f, 0.f, 0.f);
    int j = beg;
    for (; j + 4 <= end; j += 4) {
        int s0 = __ldg(&g_col[j + 0]);
        int s1 = __ldg(&g_col[j + 1]);
        int s2 = __ldg(&g_col[j + 2]);
        int s3 = __ldg(&g_col[j + 3]);
        float4 v0 = __ldg(h1v + (size_t)s0 * (HID / 4) + fo);
        float4 v1 = __ldg(h1v + (size_t)s1 * (HID / 4) + fo);
        float4 v2 = __ldg(h1v + (size_t)s2 * (HID / 4) + fo);
        float4 v3 = __ldg(h1v + (size_t)s3 * (HID / 4) + fo);
        f4add(acc, v0); f4add(acc, v1); f4add(acc, v2); f4add(acc, v3);
    }
    for (; j < end; j++) {
        int s = __ldg(&g_col[j]);
        f4add(acc, __ldg(h1v + (size_t)s * (HID / 4) + fo));
    }
    float inv = 1.0f / (float)max(end - beg, 1);
    float4 o;
    o.x = to_tf32(acc.x * inv); o.y = to_tf32(acc.y * inv);
    o.z = to_tf32(acc.z * inv); o.w = to_tf32(acc.w * inv);
    reinterpret_cast<float4*>(g_agg)[(size_t)node * (HID / 4) + fo] = o;
}

// ---------------- tf32 tensor-core SAGE GEMM ----------------
#define AS_STRIDE 36
#define BS_STRIDE 136
#define AS_BUF (128 * AS_STRIDE)
#define BS_BUF (32 * BS_STRIDE)

template <int KHALF, bool CVT>
__global__ void __launch_bounds__(256, 2)
sage_tf32(const float* __restrict__ A0, const float* __restrict__ A1,
          const float* __restrict__ W, const float* __restrict__ bias,
          float* __restrict__ C) {
    extern __shared__ float smem[];
    float* As = smem;
    float* Bs = smem + 2 * AS_BUF;

    const int tid = threadIdx.x;
    const int lane = tid & 31;
    const int wid = tid >> 5;
    const int wm = wid & 3;
    const int wn = wid >> 2;
    const int rowBase = blockIdx.x * 128;
    const int colBase = blockIdx.y * 128;
    const int NT = (2 * KHALF) / 32;

    float acc[2][8][4];
#pragma unroll
    for (int i = 0; i < 2; i++)
#pragma unroll
        for (int j = 0; j < 8; j++)
#pragma unroll
            for (int k = 0; k < 4; k++) acc[i][j][k] = 0.0f;

    auto issue = [&](int buf, int k0) {
        float* Asb = As + buf * AS_BUF;
        float* Bsb = Bs + buf * BS_BUF;
        const float* Abase = (k0 < KHALF) ? A0 : A1;
        int kb = (k0 < KHALF) ? k0 : (k0 - KHALF);
#pragma unroll
        for (int i = 0; i < 4; i++) {
            int idx = tid + 256 * i;
            int r = idx >> 3, kc = idx & 7;
            int row = rowBase + r;
            const float* src = Abase + (size_t)row * KHALF + kb + kc * 4;
            uint32_t dst = (uint32_t)__cvta_generic_to_shared(Asb + r * AS_STRIDE + kc * 4);
            int sz = (row < N_NODES) ? 16 : 0;
            asm volatile("cp.async.ca.shared.global [%0], [%1], 16, %2;"
                         :: "r"(dst), "l"(src), "r"(sz));
        }
#pragma unroll
        for (int i = 0; i < 4; i++) {
            int idx = tid + 256 * i;
            int k = idx >> 5, c4 = idx & 31;
            const float* src = W + (size_t)(k0 + k) * HID + colBase + c4 * 4;
            uint32_t dst = (uint32_t)__cvta_generic_to_shared(Bsb + k * BS_STRIDE + c4 * 4);
            asm volatile("cp.async.ca.shared.global [%0], [%1], 16;"
                         :: "r"(dst), "l"(src));
        }
        asm volatile("cp.async.commit_group;");
    };

    issue(0, 0);
    for (int t = 0; t < NT; t++) {
        if (t + 1 < NT) {
            issue((t + 1) & 1, (t + 1) * 32);
            asm volatile("cp.async.wait_group 1;");
        } else {
            asm volatile("cp.async.wait_group 0;");
        }
        __syncthreads();
        const float* Asb = As + (t & 1) * AS_BUF;
        const float* Bsb = Bs + (t & 1) * BS_BUF;
#pragma unroll
        for (int k8 = 0; k8 < 4; k8++) {
            int kb = k8 * 8;
            uint32_t a[2][4];
#pragma unroll
            for (int mt = 0; mt < 2; mt++) {
                int m = wm * 32 + mt * 16 + (lane >> 2);
                int k = kb + (lane & 3);
                a[mt][0] = __float_as_uint(Asb[m * AS_STRIDE + k]);
                a[mt][1] = __float_as_uint(Asb[(m + 8) * AS_STRIDE + k]);
                a[mt][2] = __float_as_uint(Asb[m * AS_STRIDE + k + 4]);
                a[mt][3] = __float_as_uint(Asb[(m + 8) * AS_STRIDE + k + 4]);
            }
#pragma unroll
            for (int nt = 0; nt < 8; nt++) {
                int n = wn * 64 + nt * 8 + (lane >> 2);
                int k = kb + (lane & 3);
                uint32_t b0 = __float_as_uint(Bsb[k * BS_STRIDE + n]);
                uint32_t b1 = __float_as_uint(Bsb[(k + 4) * BS_STRIDE + n]);
                mma_tf32(acc[0][nt], a[0], b0, b1);
                mma_tf32(acc[1][nt], a[1], b0, b1);
            }
        }
        __syncthreads();
    }

#pragma unroll
    for (int mt = 0; mt < 2; mt++) {
        int r0 = rowBase + wm * 32 + mt * 16 + (lane >> 2);
#pragma unroll
        for (int nt = 0; nt < 8; nt++) {
            int c = colBase + wn * 64 + nt * 8 + (lane & 3) * 2;
            float bv0 = __ldg(bias + c);
            float bv1 = __ldg(bias + c + 1);
            float v0 = fmaxf(acc[mt][nt][0] + bv0, 0.0f);
            float v1 = fmaxf(acc[mt][nt][1] + bv1, 0.0f);
            float v2 = fmaxf(acc[mt][nt][2] + bv0, 0.0f);
            float v3 = fmaxf(acc[mt][nt][3] + bv1, 0.0f);
            if (CVT) {
                v0 = to_tf32(v0); v1 = to_tf32(v1);
                v2 = to_tf32(v2); v3 = to_tf32(v3);
            }
            if (r0 < N_NODES)
                *reinterpret_cast<float2*>(C + (size_t)r0 * HID + c) = make_float2(v0, v1);
            if (r0 + 8 < N_NODES)
                *reinterpret_cast<float2*>(C + (size_t)(r0 + 8) * HID + c) = make_float2(v2, v3);
        }
    }
}

// ---------------- classifier ----------------
__global__ void classifier_k(const float* __restrict__ wc,
                             const float* __restrict__ bc,
                             float* __restrict__ out) {
    __shared__ float w[HID * N_CLASSES];
    __shared__ float hrow[8][HID];
    for (int i = threadIdx.x; i < HID * N_CLASSES; i += blockDim.x)
        w[i] = wc[i];
    __syncthreads();

    int warp = threadIdx.x >> 5;
    int lane = threadIdx.x & 31;
    int row = blockIdx.x * 8 + warp;
    if (row >= N_NODES) return;

    const float* h = g_h2 + (size_t)row * HID;
    for (int k = lane; k < HID; k += 32) hrow[warp][k] = h[k];
    __syncwarp();

    int c = lane & 15;
    int p = lane >> 4;
    float acc = 0.0f;
    int kbeg = p * (HID / 2);
#pragma unroll 8
    for (int k = kbeg; k < kbeg + HID / 2; k++)
        acc += hrow[warp][k] * w[k * N_CLASSES + c];
    acc += __shfl_xor_sync(0xffffffffu, acc, 16);
    if (lane < 16) out[(size_t)row * N_CLASSES + lane] = acc + bc[lane];
}

// ---------------- launch ----------------
extern "C" void kernel_launch(void* const* d_in, const int* in_sizes, int n_in,
                              void* d_out, int out_size) {
    const float* x    = (const float*)d_in[0];
    const int*   ei   = (const int*)d_in[1];
    const float* w1_l = (const float*)d_in[2];
    const float* b1_l = (const float*)d_in[3];
    const float* w1_r = (const float*)d_in[4];
    const float* w2_l = (const float*)d_in[5];
    const float* b2_l = (const float*)d_in[6];
    const float* w2_r = (const float*)d_in[7];
    const float* wc   = (const float*)d_in[8];
    const float* bc   = (const float*)d_in[9];
    float* out = (float*)d_out;

    // resolve REAL device addresses (GB300 ATS pitfall: never pass symbols as args)
    void *p_agg, *p_h1, *p_h2, *p_xt, *p_w1t, *p_w2t;
    cudaGetSymbolAddress(&p_agg, g_agg);
    cudaGetSymbolAddress(&p_h1,  g_h1);
    cudaGetSymbolAddress(&p_h2,  g_h2);
    cudaGetSymbolAddress(&p_xt,  g_xt);
    cudaGetSymbolAddress(&p_w1t, g_w1t);
    cudaGetSymbolAddress(&p_w2t, g_w2t);

    const int SMEM = (2 * AS_BUF + 2 * BS_BUF) * 4;
    cudaFuncSetAttribute(sage_tf32<IN_DIM, true>,
                         cudaFuncAttributeMaxDynamicSharedMemorySize, SMEM);
    cudaFuncSetAttribute(sage_tf32<HID, false>,
                         cudaFuncAttributeMaxDynamicSharedMemorySize, SMEM);

    // ---- CSR build ----
    zero_cnt<<<(N_NODES + 255) / 256, 256>>>();
    hist_kernel<<<(N_EDGES + 255) / 256, 256>>>(ei);
    block_reduce_k<<<N_SBLOCKS, SCAN_BLOCK>>>();
    scan_blocksums_k<<<1, 256>>>();
    block_scan_k<<<N_SBLOCKS, SCAN_BLOCK>>>();
    fill_kernel<<<(N_EDGES + 255) / 256, 256>>>(ei);

    // ---- tf32 input conversions ----
    cvt_concat<<<(2 * IN_DIM * HID + 255) / 256, 256>>>((float*)p_w1t, w1_l, w1_r, IN_DIM * HID);
    cvt_concat<<<(2 * HID * HID + 255) / 256, 256>>>((float*)p_w2t, w2_l, w2_r, HID * HID);
    cvt_copy<<<(N_NODES * IN_DIM + 255) / 256, 256>>>((float*)p_xt, x, N_NODES * IN_DIM);

    // ---- layer 1 ----
    gather_mean_128<<<(N_NODES * 32 + 255) / 256, 256>>>(x);
    {
        dim3 grid((N_NODES + 127) / 128, HID / 128);
        sage_tf32<IN_DIM, true><<<grid, 256, SMEM>>>(
            (const float*)p_agg, (const float*)p_xt, (const float*)p_w1t, b1_l, (float*)p_h1);
    }

    // ---- layer 2 ----
    gather_mean_256<<<(N_NODES * 2 * 32 + 255) / 256, 256>>>();
    {
        dim3 grid((N_NODES + 127) / 128, HID / 128);
        sage_tf32<HID, false><<<grid, 256, SMEM>>>(
            (const float*)p_agg, (const float*)p_h1, (const float*)p_w2t, b2_l, (float*)p_h2);
    }

    // ---- classifier ----
    classifier_k<<<(N_NODES + 7) / 8, 256>>>(wc, bc, out);
}

// round 13
// speedup vs baseline: 1.1808x; 1.0537x over previous
#include <cuda_runtime.h>
#include <stdint.h>

#define N_NODES 50000
#define N_EDGES 600000
#define IN_DIM 128
#define HID 256
#define N_CLASSES 16

#define SCAN_BLOCK 256
#define N_SBLOCKS ((N_NODES + SCAN_BLOCK - 1) / SCAN_BLOCK)   // 196

// ---------------- device scratch (no allocation allowed) ----------------
__device__ int   g_cnt[N_NODES];
__device__ int   g_blockoff[N_SBLOCKS];
__device__ int   g_rowptr[N_NODES + 1];
__device__ int   g_cursor[N_NODES];
__device__ int   g_col[N_EDGES];                  // src ids bucketed by dst
__device__ float g_agg[(size_t)N_NODES * HID];
__device__ float g_h1[(size_t)N_NODES * HID];
__device__ float g_h2[(size_t)N_NODES * HID];
__device__ float g_w1t[2 * IN_DIM * HID];         // [w1_l ; w1_r] tf32
__device__ float g_w2t[2 * HID * HID];            // [w2_l ; w2_r] tf32

// ---------------- helpers ----------------
__device__ __forceinline__ float to_tf32(float x) {
    uint32_t u;
    asm("cvt.rna.tf32.f32 %0, %1;" : "=r"(u) : "f"(x));
    return __uint_as_float(u);
}

__device__ __forceinline__ void mma_tf32(float* d, const uint32_t* a, uint32_t b0, uint32_t b1) {
    asm volatile(
        "mma.sync.aligned.m16n8k8.row.col.f32.tf32.tf32.f32 "
        "{%0,%1,%2,%3}, {%4,%5,%6,%7}, {%8,%9}, {%0,%1,%2,%3};"
        : "+f"(d[0]), "+f"(d[1]), "+f"(d[2]), "+f"(d[3])
        : "r"(a[0]), "r"(a[1]), "r"(a[2]), "r"(a[3]), "r"(b0), "r"(b1));
}

__device__ __forceinline__ void f4add(float4& a, const float4 b) {
    a.x += b.x; a.y += b.y; a.z += b.z; a.w += b.w;
}

// ---------------- launch 1: zero cnt + convert all weights to tf32 ----------------
__global__ void prep_k(const float* __restrict__ w1_l, const float* __restrict__ w1_r,
                       const float* __restrict__ w2_l, const float* __restrict__ w2_r) {
    int i = blockIdx.x * blockDim.x + threadIdx.x;
    if (i < N_NODES) g_cnt[i] = 0;
    const int H1 = IN_DIM * HID;
    if (i < 2 * H1)
        g_w1t[i] = to_tf32(i < H1 ? w1_l[i] : w1_r[i - H1]);
    const int H2 = HID * HID;
    if (i < 2 * H2)
        g_w2t[i] = to_tf32(i < H2 ? w2_l[i] : w2_r[i - H2]);
}

// ---------------- CSR build ----------------
__global__ void hist_kernel(const int* __restrict__ ei) {
    int e = blockIdx.x * blockDim.x + threadIdx.x;
    if (e >= N_EDGES) return;
    int d = min(max(ei[N_EDGES + e], 0), N_NODES - 1);
    atomicAdd(&g_cnt[d], 1);
}
__global__ void block_reduce_k() {
    __shared__ int sm[SCAN_BLOCK];
    int i = blockIdx.x * SCAN_BLOCK + threadIdx.x;
    sm[threadIdx.x] = (i < N_NODES) ? g_cnt[i] : 0;
    __syncthreads();
#pragma unroll
    for (int o = SCAN_BLOCK / 2; o > 0; o >>= 1) {
        if (threadIdx.x < o) sm[threadIdx.x] += sm[threadIdx.x + o];
        __syncthreads();
    }
    if (threadIdx.x == 0) g_blockoff[blockIdx.x] = sm[0];
}
__global__ void scan_blocksums_k() {
    __shared__ int sm[256];
    int t = threadIdx.x;
    int v = (t < N_SBLOCKS) ? g_blockoff[t] : 0;
    sm[t] = v;
    __syncthreads();
#pragma unroll
    for (int o = 1; o < 256; o <<= 1) {
        int u = (t >= o) ? sm[t - o] : 0;
        __syncthreads();
        sm[t] += u;
        __syncthreads();
    }
    if (t < N_SBLOCKS) g_blockoff[t] = sm[t] - v;
}
__global__ void block_scan_k() {
    __shared__ int sm[SCAN_BLOCK];
    int i = blockIdx.x * SCAN_BLOCK + threadIdx.x;
    int v = (i < N_NODES) ? g_cnt[i] : 0;
    sm[threadIdx.x] = v;
    __syncthreads();
#pragma unroll
    for (int o = 1; o < SCAN_BLOCK; o <<= 1) {
        int u = (threadIdx.x >= o) ? sm[threadIdx.x - o] : 0;
        __syncthreads();
        sm[threadIdx.x] += u;
        __syncthreads();
    }
    if (i < N_NODES) {
        int excl = sm[threadIdx.x] - v + g_blockoff[blockIdx.x];
        g_rowptr[i] = excl;
        g_cursor[i] = excl;
    }
    if (i == 0) g_rowptr[N_NODES] = N_EDGES;
}
__global__ void fill_kernel(const int* __restrict__ ei) {
    int e = blockIdx.x * blockDim.x + threadIdx.x;
    if (e >= N_EDGES) return;
    int s = min(max(ei[e], 0), N_NODES - 1);
    int d = min(max(ei[N_EDGES + e], 0), N_NODES - 1);
    int pos = atomicAdd(&g_cursor[d], 1);
    g_col[pos] = s;
}

// ---------------- gather mean (CSR) ----------------
__global__ void gather_mean_128(const float* __restrict__ feat) {
    int w = (blockIdx.x * blockDim.x + threadIdx.x) >> 5;
    int lane = threadIdx.x & 31;
    if (w >= N_NODES) return;
    int beg = g_rowptr[w], end = g_rowptr[w + 1];
    float4 acc = make_float4(0.f, 0.f, 0.f, 0.f);
    int j = beg;
    for (; j + 4 <= end; j += 4) {
        int s0 = __ldg(&g_col[j + 0]);
        int s1 = __ldg(&g_col[j + 1]);
        int s2 = __ldg(&g_col[j + 2]);
        int s3 = __ldg(&g_col[j + 3]);
        float4 v0 = __ldg(reinterpret_cast<const float4*>(feat + (size_t)s0 * IN_DIM) + lane);
        float4 v1 = __ldg(reinterpret_cast<const float4*>(feat + (size_t)s1 * IN_DIM) + lane);
        float4 v2 = __ldg(reinterpret_cast<const float4*>(feat + (size_t)s2 * IN_DIM) + lane);
        float4 v3 = __ldg(reinterpret_cast<const float4*>(feat + (size_t)s3 * IN_DIM) + lane);
        f4add(acc, v0); f4add(acc, v1); f4add(acc, v2); f4add(acc, v3);
    }
    for (; j < end; j++) {
        int s = __ldg(&g_col[j]);
        float4 v = __ldg(reinterpret_cast<const float4*>(feat + (size_t)s * IN_DIM) + lane);
        f4add(acc, v);
    }
    float inv = 1.0f / (float)max(end - beg, 1);
    float4 o;
    o.x = to_tf32(acc.x * inv); o.y = to_tf32(acc.y * inv);
    o.z = to_tf32(acc.z * inv); o.w = to_tf32(acc.w * inv);
    reinterpret_cast<float4*>(g_agg + (size_t)w * IN_DIM)[lane] = o;
}

// two warps per node: warp-half h handles float4s [h*32 .. h*32+31] of the 256-wide row
__global__ void gather_mean_256() {
    int gw = (blockIdx.x * blockDim.x + threadIdx.x) >> 5;
    int node = gw >> 1;
    int half = gw & 1;
    int lane = threadIdx.x & 31;
    if (node >= N_NODES) return;
    int beg = g_rowptr[node], end = g_rowptr[node + 1];
    int fo = half * 32 + lane;
    const float4* h1v = reinterpret_cast<const float4*>(g_h1);
    float4 acc = make_float4(0.f, 0.f, 0.f, 0.f);
    int j = beg;
    for (; j + 4 <= end; j += 4) {
        int s0 = __ldg(&g_col[j + 0]);
        int s1 = __ldg(&g_col[j + 1]);
        int s2 = __ldg(&g_col[j + 2]);
        int s3 = __ldg(&g_col[j + 3]);
        float4 v0 = __ldg(h1v + (size_t)s0 * (HID / 4) + fo);
        float4 v1 = __ldg(h1v + (size_t)s1 * (HID / 4) + fo);
        float4 v2 = __ldg(h1v + (size_t)s2 * (HID / 4) + fo);
        float4 v3 = __ldg(h1v + (size_t)s3 * (HID / 4) + fo);
        f4add(acc, v0); f4add(acc, v1); f4add(acc, v2); f4add(acc, v3);
    }
    for (; j < end; j++) {
        int s = __ldg(&g_col[j]);
        f4add(acc, __ldg(h1v + (size_t)s * (HID / 4) + fo));
    }
    float inv = 1.0f / (float)max(end - beg, 1);
    float4 o;
    o.x = to_tf32(acc.x * inv); o.y = to_tf32(acc.y * inv);
    o.z = to_tf32(acc.z * inv); o.w = to_tf32(acc.w * inv);
    reinterpret_cast<float4*>(g_agg)[(size_t)node * (HID / 4) + fo] = o;
}

// ---------------- tf32 tensor-core SAGE GEMM, BM=128 BN=256 BK=32, 512 thr ----------------
// C[M,256] = relu( Avirt[M, 2*KHALF] @ W[2*KHALF, 256] + bias )
#define AS_STRIDE 36
#define BS_STRIDE 264
#define AS_BUF (128 * AS_STRIDE)
#define BS_BUF (32 * BS_STRIDE)

template <int KHALF, bool CVT_A, bool CVT_OUT>
__global__ void __launch_bounds__(512, 1)
sage_tf32(const float* __restrict__ A0, const float* __restrict__ A1,
          const float* __restrict__ W, const float* __restrict__ bias,
          float* __restrict__ C) {
    extern __shared__ float smem[];
    float* As = smem;                 // 2 x 128 x 36
    float* Bs = smem + 2 * AS_BUF;    // 2 x 32 x 264

    const int tid = threadIdx.x;
    const int lane = tid & 31;
    const int wid = tid >> 5;
    const int wm = wid & 3;           // 4 m-warps x 32 rows
    const int wn = wid >> 2;          // 4 n-warps x 64 cols
    const int rowBase = blockIdx.x * 128;
    const int NT = (2 * KHALF) / 32;

    float acc[2][8][4];
#pragma unroll
    for (int i = 0; i < 2; i++)
#pragma unroll
        for (int j = 0; j < 8; j++)
#pragma unroll
            for (int k = 0; k < 4; k++) acc[i][j][k] = 0.0f;

    auto issue = [&](int buf, int k0) {
        float* Asb = As + buf * AS_BUF;
        float* Bsb = Bs + buf * BS_BUF;
        const float* Abase = (k0 < KHALF) ? A0 : A1;
        int kb = (k0 < KHALF) ? k0 : (k0 - KHALF);
        // A tile: 128 rows x 32 k = 1024 float4, 512 threads -> 2 iters
#pragma unroll
        for (int i = 0; i < 2; i++) {
            int idx = tid + 512 * i;
            int r = idx >> 3, kc = idx & 7;
            int row = rowBase + r;
            const float* src = Abase + (size_t)row * KHALF + kb + kc * 4;
            uint32_t dst = (uint32_t)__cvta_generic_to_shared(Asb + r * AS_STRIDE + kc * 4);
            int sz = (row < N_NODES) ? 16 : 0;
            asm volatile("cp.async.ca.shared.global [%0], [%1], 16, %2;"
                         :: "r"(dst), "l"(src), "r"(sz));
        }
        // B tile: 32 k x 256 cols = 2048 float4, 512 threads -> 4 iters
#pragma unroll
        for (int i = 0; i < 4; i++) {
            int idx = tid + 512 * i;
            int k = idx >> 6, c4 = idx & 63;
            const float* src = W + (size_t)(k0 + k) * HID + c4 * 4;
            uint32_t dst = (uint32_t)__cvta_generic_to_shared(Bsb + k * BS_STRIDE + c4 * 4);
            asm volatile("cp.async.ca.shared.global [%0], [%1], 16;"
                         :: "r"(dst), "l"(src));
        }
        asm volatile("cp.async.commit_group;");
    };

    issue(0, 0);
    for (int t = 0; t < NT; t++) {
        if (t + 1 < NT) {
            issue((t + 1) & 1, (t + 1) * 32);
            asm volatile("cp.async.wait_group 1;");
        } else {
            asm volatile("cp.async.wait_group 0;");
        }
        __syncthreads();
        const float* Asb = As + (t & 1) * AS_BUF;
        const float* Bsb = Bs + (t & 1) * BS_BUF;
#pragma unroll
        for (int k8 = 0; k8 < 4; k8++) {
            int kb = k8 * 8;
            uint32_t a[2][4];
#pragma unroll
            for (int mt = 0; mt < 2; mt++) {
                int m = wm * 32 + mt * 16 + (lane >> 2);
                int k = kb + (lane & 3);
                float a0 = Asb[m * AS_STRIDE + k];
                float a1 = Asb[(m + 8) * AS_STRIDE + k];
                float a2 = Asb[m * AS_STRIDE + k + 4];
                float a3 = Asb[(m + 8) * AS_STRIDE + k + 4];
                if (CVT_A) { a0 = to_tf32(a0); a1 = to_tf32(a1); a2 = to_tf32(a2); a3 = to_tf32(a3); }
                a[mt][0] = __float_as_uint(a0);
                a[mt][1] = __float_as_uint(a1);
                a[mt][2] = __float_as_uint(a2);
                a[mt][3] = __float_as_uint(a3);
            }
#pragma unroll
            for (int nt = 0; nt < 8; nt++) {
                int n = wn * 64 + nt * 8 + (lane >> 2);
                int k = kb + (lane & 3);
                uint32_t b0 = __float_as_uint(Bsb[k * BS_STRIDE + n]);
                uint32_t b1 = __float_as_uint(Bsb[(k + 4) * BS_STRIDE + n]);
                mma_tf32(acc[0][nt], a[0], b0, b1);
                mma_tf32(acc[1][nt], a[1], b0, b1);
            }
        }
        __syncthreads();
    }

#pragma unroll
    for (int mt = 0; mt < 2; mt++) {
        int r0 = rowBase + wm * 32 + mt * 16 + (lane >> 2);
#pragma unroll
        for (int nt = 0; nt < 8; nt++) {
            int c = wn * 64 + nt * 8 + (lane & 3) * 2;
            float bv0 = __ldg(bias + c);
            float bv1 = __ldg(bias + c + 1);
            float v0 = fmaxf(acc[mt][nt][0] + bv0, 0.0f);
            float v1 = fmaxf(acc[mt][nt][1] + bv1, 0.0f);
            float v2 = fmaxf(acc[mt][nt][2] + bv0, 0.0f);
            float v3 = fmaxf(acc[mt][nt][3] + bv1, 0.0f);
            if (CVT_OUT) {
                v0 = to_tf32(v0); v1 = to_tf32(v1);
                v2 = to_tf32(v2); v3 = to_tf32(v3);
            }
            if (r0 < N_NODES)
                *reinterpret_cast<float2*>(C + (size_t)r0 * HID + c) = make_float2(v0, v1);
            if (r0 + 8 < N_NODES)
                *reinterpret_cast<float2*>(C + (size_t)(r0 + 8) * HID + c) = make_float2(v2, v3);
        }
    }
}

// ---------------- classifier ----------------
__global__ void classifier_k(const float* __restrict__ wc,
                             const float* __restrict__ bc,
                             float* __restrict__ out) {
    __shared__ float w[HID * N_CLASSES];
    __shared__ float hrow[8][HID];
    for (int i = threadIdx.x; i < HID * N_CLASSES; i += blockDim.x)
        w[i] = wc[i];
    __syncthreads();

    int warp = threadIdx.x >> 5;
    int lane = threadIdx.x & 31;
    int row = blockIdx.x * 8 + warp;
    if (row >= N_NODES) return;

    const float* h = g_h2 + (size_t)row * HID;
    for (int k = lane; k < HID; k += 32) hrow[warp][k] = h[k];
    __syncwarp();

    int c = lane & 15;
    int p = lane >> 4;
    float acc = 0.0f;
    int kbeg = p * (HID / 2);
#pragma unroll 8
    for (int k = kbeg; k < kbeg + HID / 2; k++)
        acc += hrow[warp][k] * w[k * N_CLASSES + c];
    acc += __shfl_xor_sync(0xffffffffu, acc, 16);
    if (lane < 16) out[(size_t)row * N_CLASSES + lane] = acc + bc[lane];
}

// ---------------- launch ----------------
extern "C" void kernel_launch(void* const* d_in, const int* in_sizes, int n_in,
                              void* d_out, int out_size) {
    const float* x    = (const float*)d_in[0];
    const int*   ei   = (const int*)d_in[1];
    const float* w1_l = (const float*)d_in[2];
    const float* b1_l = (const float*)d_in[3];
    const float* w1_r = (const float*)d_in[4];
    const float* w2_l = (const float*)d_in[5];
    const float* b2_l = (const float*)d_in[6];
    const float* w2_r = (const float*)d_in[7];
    const float* wc   = (const float*)d_in[8];
    const float* bc   = (const float*)d_in[9];
    float* out = (float*)d_out;

    // resolve REAL device addresses (GB300 ATS pitfall: never pass symbols as args)
    void *p_agg, *p_h1, *p_h2, *p_w1t, *p_w2t;
    cudaGetSymbolAddress(&p_agg, g_agg);
    cudaGetSymbolAddress(&p_h1,  g_h1);
    cudaGetSymbolAddress(&p_h2,  g_h2);
    cudaGetSymbolAddress(&p_w1t, g_w1t);
    cudaGetSymbolAddress(&p_w2t, g_w2t);

    const int SMEM = (2 * AS_BUF + 2 * BS_BUF) * 4;   // 104448 B
    cudaFuncSetAttribute(sage_tf32<IN_DIM, true, true>,
                         cudaFuncAttributeMaxDynamicSharedMemorySize, SMEM);
    cudaFuncSetAttribute(sage_tf32<HID, false, false>,
                         cudaFuncAttributeMaxDynamicSharedMemorySize, SMEM);

    // ---- prep: zero cnt + weight tf32 cvts ----
    prep_k<<<(2 * HID * HID + 255) / 256, 256>>>(w1_l, w1_r, w2_l, w2_r);

    // ---- CSR build ----
    hist_kernel<<<(N_EDGES + 255) / 256, 256>>>(ei);
    block_reduce_k<<<N_SBLOCKS, SCAN_BLOCK>>>();
    scan_blocksums_k<<<1, 256>>>();
    block_scan_k<<<N_SBLOCKS, SCAN_BLOCK>>>();
    fill_kernel<<<(N_EDGES + 255) / 256, 256>>>(ei);

    // ---- layer 1 ----
    gather_mean_128<<<(N_NODES * 32 + 255) / 256, 256>>>(x);
    {
        dim3 grid((N_NODES + 127) / 128, 1);
        sage_tf32<IN_DIM, true, true><<<grid, 512, SMEM>>>(
            (const float*)p_agg, x, (const float*)p_w1t, b1_l, (float*)p_h1);
    }

    // ---- layer 2 ----
    gather_mean_256<<<(N_NODES * 2 * 32 + 255) / 256, 256>>>();
    {
        dim3 grid((N_NODES + 127) / 128, 1);
        sage_tf32<HID, false, false><<<grid, 512, SMEM>>>(
            (const float*)p_agg, (const float*)p_h1, (const float*)p_w2t, b2_l, (float*)p_h2);
    }

    // ---- classifier ----
    classifier_k<<<(N_NODES + 7) / 8, 256>>>(wc, bc, out);
}